// round 7
// baseline (speedup 1.0000x reference)
#include <cuda_runtime.h>
#include <cuda_bf16.h>

// Problem constants (fixed by the reference setup)
#define HH 240
#define WW 304
#define IN_CH 16
#define OUT_CH 32
#define CIN 18            // pos + neg + 16 features
#define CPAD 20           // padded per-pixel channel stride: [pos,neg,f0..f15,cnt,pad]
#define BB 8
#define NPIX (BB * HH * WW)          // 583680
#define NMAX (BB * 65536)            // 524288 events
#define WSIZE (3 * 3 * CIN * OUT_CH) // 5184 weights

// Scratch (device globals: no allocation allowed in kernel_launch)
__device__ float g_dense[(size_t)NPIX * CPAD];   // ~46.7 MB accumulator (+count)
__device__ float g_conv [(size_t)NPIX * OUT_CH]; // ~74.7 MB conv output
__device__ int   g_key  [NMAX];

// ---------------------------------------------------------------------------
// 0) Zero the accumulator (must happen every graph replay)
// ---------------------------------------------------------------------------
__global__ void zero_dense_kernel() {
    const size_t n4 = (size_t)NPIX * CPAD / 4;
    size_t i = (size_t)blockIdx.x * blockDim.x + threadIdx.x;
    float4* p = reinterpret_cast<float4*>(g_dense);
    if (i < n4) p[i] = make_float4(0.f, 0.f, 0.f, 0.f);
}

// ---------------------------------------------------------------------------
// 1) Scatter: per-event vector atomics into the dense grid; cache key.
//    offsets buffer may be int32 or int64 (JAX x64 off silently downcasts);
//    detect at runtime: values are positive < 2^31, so for a little-endian
//    int64 buffer the second 32-bit word is 0.
// ---------------------------------------------------------------------------
__global__ void scatter_kernel(const float* __restrict__ events,
                               const float* __restrict__ features,
                               const int* __restrict__ offsets_raw,
                               int n, int nb) {
    int i = blockIdx.x * blockDim.x + threadIdx.x;
    if (i >= n) return;

    bool is64 = (nb > 1) ? (__ldg(&offsets_raw[1]) == 0) : false;

    float4 ev = *reinterpret_cast<const float4*>(events + (size_t)i * 4);

    // batch = searchsorted(offsets, i, side='right') = #(offsets[j] <= i)
    int b = 0;
    #pragma unroll
    for (int j = 0; j < BB; j++) {
        if (j < nb) {
            long long oj = is64
                ? __ldg(reinterpret_cast<const long long*>(offsets_raw) + j)
                : (long long)__ldg(&offsets_raw[j]);
            if (oj <= (long long)i) b++;
        }
    }

    // round-half-to-even like jnp.round, then clip
    int yi = __float2int_rn(ev.y * (float)HH);
    int xi = __float2int_rn(ev.x * (float)WW);
    yi = min(max(yi, 0), HH - 1);
    xi = min(max(xi, 0), WW - 1);
    int key = (b * HH + yi) * WW + xi;
    g_key[i] = key;

    float pos = ev.w;
    float neg = 1.0f - pos;

    const float4* f = reinterpret_cast<const float4*>(features + (size_t)i * IN_CH);
    float4 f0 = f[0], f1 = f[1], f2 = f[2], f3 = f[3];

    float* d = g_dense + (size_t)key * CPAD;
    atomicAdd(reinterpret_cast<float4*>(d +  0), make_float4(pos,  neg,  f0.x, f0.y));
    atomicAdd(reinterpret_cast<float4*>(d +  4), make_float4(f0.z, f0.w, f1.x, f1.y));
    atomicAdd(reinterpret_cast<float4*>(d +  8), make_float4(f1.z, f1.w, f2.x, f2.y));
    atomicAdd(reinterpret_cast<float4*>(d + 12), make_float4(f2.z, f2.w, f3.x, f3.y));
    atomicAdd(reinterpret_cast<float4*>(d + 16), make_float4(f3.z, f3.w, 1.0f, 0.0f));
}

// ---------------------------------------------------------------------------
// 2) Normalize: dense /= max(cnt, 1)
// ---------------------------------------------------------------------------
__global__ void normalize_kernel() {
    int p = blockIdx.x * blockDim.x + threadIdx.x;
    if (p >= NPIX) return;
    float* d = g_dense + (size_t)p * CPAD;
    float4 a0 = *reinterpret_cast<float4*>(d + 0);
    float4 a1 = *reinterpret_cast<float4*>(d + 4);
    float4 a2 = *reinterpret_cast<float4*>(d + 8);
    float4 a3 = *reinterpret_cast<float4*>(d + 12);
    float4 a4 = *reinterpret_cast<float4*>(d + 16); // f14, f15, cnt, pad
    float inv = 1.0f / fmaxf(a4.z, 1.0f);
    a0.x *= inv; a0.y *= inv; a0.z *= inv; a0.w *= inv;
    a1.x *= inv; a1.y *= inv; a1.z *= inv; a1.w *= inv;
    a2.x *= inv; a2.y *= inv; a2.z *= inv; a2.w *= inv;
    a3.x *= inv; a3.y *= inv; a3.z *= inv; a3.w *= inv;
    a4.x *= inv; a4.y *= inv;
    *reinterpret_cast<float4*>(d + 0)  = a0;
    *reinterpret_cast<float4*>(d + 4)  = a1;
    *reinterpret_cast<float4*>(d + 8)  = a2;
    *reinterpret_cast<float4*>(d + 12) = a3;
    *reinterpret_cast<float4*>(d + 16) = a4;
}

// ---------------------------------------------------------------------------
// 3) Direct 3x3 conv, SAME padding, fp32. Weights HWIO in smem (broadcast LDS).
//    One thread per pixel, 32 out channels in registers.
// ---------------------------------------------------------------------------
__global__ __launch_bounds__(256) void conv_kernel(const float* __restrict__ weight) {
    __shared__ float sw[WSIZE]; // 20736 B
    for (int i = threadIdx.x; i < WSIZE; i += blockDim.x) sw[i] = weight[i];
    __syncthreads();

    int p = blockIdx.x * blockDim.x + threadIdx.x;
    if (p >= NPIX) return;

    int b   = p / (HH * WW);
    int rem = p - b * HH * WW;
    int y   = rem / WW;
    int x   = rem - y * WW;

    float acc[OUT_CH];
    #pragma unroll
    for (int oc = 0; oc < OUT_CH; oc++) acc[oc] = 0.0f;

    #pragma unroll
    for (int ky = 0; ky < 3; ky++) {
        int iy = y + ky - 1;
        if ((unsigned)iy >= (unsigned)HH) continue;
        #pragma unroll
        for (int kx = 0; kx < 3; kx++) {
            int ix = x + kx - 1;
            if ((unsigned)ix >= (unsigned)WW) continue;

            const float* in = g_dense + ((size_t)(b * HH + iy) * WW + ix) * CPAD;
            float v[CIN];
            float4 a0 = *reinterpret_cast<const float4*>(in + 0);
            float4 a1 = *reinterpret_cast<const float4*>(in + 4);
            float4 a2 = *reinterpret_cast<const float4*>(in + 8);
            float4 a3 = *reinterpret_cast<const float4*>(in + 12);
            float2 a4 = *reinterpret_cast<const float2*>(in + 16);
            v[0]=a0.x; v[1]=a0.y; v[2]=a0.z; v[3]=a0.w;
            v[4]=a1.x; v[5]=a1.y; v[6]=a1.z; v[7]=a1.w;
            v[8]=a2.x; v[9]=a2.y; v[10]=a2.z; v[11]=a2.w;
            v[12]=a3.x; v[13]=a3.y; v[14]=a3.z; v[15]=a3.w;
            v[16]=a4.x; v[17]=a4.y;

            const float* wr = sw + (ky * 3 + kx) * CIN * OUT_CH;
            #pragma unroll
            for (int c = 0; c < CIN; c++) {
                float vv = v[c];
                const float4* w4 = reinterpret_cast<const float4*>(wr + c * OUT_CH);
                #pragma unroll
                for (int q = 0; q < OUT_CH / 4; q++) {
                    float4 w = w4[q];
                    acc[q*4+0] = fmaf(vv, w.x, acc[q*4+0]);
                    acc[q*4+1] = fmaf(vv, w.y, acc[q*4+1]);
                    acc[q*4+2] = fmaf(vv, w.z, acc[q*4+2]);
                    acc[q*4+3] = fmaf(vv, w.w, acc[q*4+3]);
                }
            }
        }
    }

    float* out = g_conv + (size_t)p * OUT_CH;
    #pragma unroll
    for (int q = 0; q < OUT_CH / 4; q++) {
        *reinterpret_cast<float4*>(out + q * 4) =
            make_float4(acc[q*4+0], acc[q*4+1], acc[q*4+2], acc[q*4+3]);
    }
}

// ---------------------------------------------------------------------------
// 4) Gather: f[i] = conv[key[i]] + bias   (8 threads / event, float4 each)
// ---------------------------------------------------------------------------
__global__ void gather_kernel(const float* __restrict__ bias,
                              float* __restrict__ out, int n) {
    int t = blockIdx.x * blockDim.x + threadIdx.x;
    if (t >= n * 8) return;
    int e = t >> 3;
    int q = t & 7;
    int key = g_key[e];
    float4 v = *reinterpret_cast<const float4*>(g_conv + (size_t)key * OUT_CH + q * 4);
    float4 bb = *reinterpret_cast<const float4*>(bias + q * 4);
    v.x += bb.x; v.y += bb.y; v.z += bb.z; v.w += bb.w;
    *reinterpret_cast<float4*>(out + (size_t)e * OUT_CH + q * 4) = v;
}

// ---------------------------------------------------------------------------
extern "C" void kernel_launch(void* const* d_in, const int* in_sizes, int n_in,
                              void* d_out, int out_size) {
    // Identify inputs by element count (robust to ordering):
    //   events:   N*4   (2,097,152)
    //   features: N*16  (8,388,608)
    //   weight:   5184
    //   bias:     32
    //   offsets:  8 (elements; dtype may be int32 or int64)
    const float* events   = nullptr;
    const float* features = nullptr;
    const float* weight   = nullptr;
    const float* bias     = nullptr;
    const int*   offsets  = nullptr;
    int n = 0, nb = 0;

    // find the two large buffers
    int big0 = -1, big1 = -1;
    for (int i = 0; i < n_in; i++) {
        int s = in_sizes[i];
        if (s == WSIZE)            weight  = (const float*)d_in[i];
        else if (s == OUT_CH)      bias    = (const float*)d_in[i];
        else if (s <= 64)        { offsets = (const int*)d_in[i]; nb = s; }
        else if (big0 < 0)         big0 = i;
        else                       big1 = i;
    }
    // events has 4 cols, features 16 cols: features is the larger
    if (in_sizes[big0] > in_sizes[big1]) { int t = big0; big0 = big1; big1 = t; }
    events   = (const float*)d_in[big0];
    features = (const float*)d_in[big1];
    n = in_sizes[big0] / 4;
    if (nb > BB) nb = BB;

    const int T = 256;

    // 0) zero accumulator
    {
        size_t n4 = (size_t)NPIX * CPAD / 4;
        int blocks = (int)((n4 + T - 1) / T);
        zero_dense_kernel<<<blocks, T>>>();
    }
    // 1) scatter
    scatter_kernel<<<(n + T - 1) / T, T>>>(events, features, offsets, n, nb);
    // 2) normalize
    normalize_kernel<<<(NPIX + T - 1) / T, T>>>();
    // 3) conv
    conv_kernel<<<(NPIX + T - 1) / T, T>>>(weight);
    // 4) gather + bias
    gather_kernel<<<(n * 8 + T - 1) / T, T>>>(bias, (float*)d_out, n);
}